// round 8
// baseline (speedup 1.0000x reference)
#include <cuda_runtime.h>
#include <cuda_bf16.h>
#include <cuda_fp16.h>
#include <cstdint>
#include <math.h>

#define BSZ 2
#define HH 64
#define WW 80
#define NQ (HH*WW)          // 5120
#define EE 576
#define HEADS 18
#define HD 32
#define NPTS 12
#define NFR 3
#define DDEP 5
#define NV (NQ*DDEP)        // 25600
#define NOFF (HEADS*NPTS*3) // 648
#define NATT (HEADS*NPTS)   // 216

// ---------------- scratch (device globals; no allocation allowed) ----------
__device__ float g_offs[(size_t)BSZ*NQ*NOFF];
__device__ float g_attn[(size_t)BSZ*NQ*NATT];

__device__ __align__(128) __half        g_vf  [(size_t)BSZ*NV*EE];   // projected v, fp16
__device__ __align__(128) __nv_bfloat16 g_vh  [(size_t)BSZ*NV*EE];
__device__ __align__(128) __nv_bfloat16 g_vl  [(size_t)BSZ*NV*EE];
__device__ __align__(128) __nv_bfloat16 g_qh  [(size_t)BSZ*NQ*EE];
__device__ __align__(128) __nv_bfloat16 g_ql  [(size_t)BSZ*NQ*EE];
__device__ __align__(128) __nv_bfloat16 g_sph [(size_t)BSZ*NQ*EE];
__device__ __align__(128) __nv_bfloat16 g_spl [(size_t)BSZ*NQ*EE];
__device__ __align__(128) __nv_bfloat16 g_wvh [(size_t)EE*EE];
__device__ __align__(128) __nv_bfloat16 g_wvl [(size_t)EE*EE];
__device__ __align__(128) __nv_bfloat16 g_woh [(size_t)EE*NOFF];
__device__ __align__(128) __nv_bfloat16 g_wol [(size_t)EE*NOFF];
__device__ __align__(128) __nv_bfloat16 g_wah [(size_t)EE*NATT];
__device__ __align__(128) __nv_bfloat16 g_wal [(size_t)EE*NATT];
__device__ __align__(128) __nv_bfloat16 g_wuh [(size_t)EE*EE];
__device__ __align__(128) __nv_bfloat16 g_wul [(size_t)EE*EE];

// ================= helpers =================================================
__device__ __forceinline__ uint32_t smem_u32(const void* p) {
    uint32_t a;
    asm("{ .reg .u64 t; cvta.to.shared.u64 t, %1; cvt.u32.u64 %0, t; }" : "=r"(a) : "l"(p));
    return a;
}
__device__ __forceinline__ void ldsm_x4(uint32_t* r, uint32_t addr) {
    asm volatile("ldmatrix.sync.aligned.m8n8.x4.shared.b16 {%0,%1,%2,%3}, [%4];"
                 : "=r"(r[0]), "=r"(r[1]), "=r"(r[2]), "=r"(r[3]) : "r"(addr));
}
__device__ __forceinline__ void ldsm_x4_t(uint32_t* r, uint32_t addr) {
    asm volatile("ldmatrix.sync.aligned.m8n8.x4.trans.shared.b16 {%0,%1,%2,%3}, [%4];"
                 : "=r"(r[0]), "=r"(r[1]), "=r"(r[2]), "=r"(r[3]) : "r"(addr));
}
__device__ __forceinline__ void mma_bf16(float* c, const uint32_t* a, const uint32_t* b) {
    asm volatile(
        "mma.sync.aligned.m16n8k16.row.col.f32.bf16.bf16.f32 "
        "{%0,%1,%2,%3}, {%4,%5,%6,%7}, {%8,%9}, {%0,%1,%2,%3};"
        : "+f"(c[0]), "+f"(c[1]), "+f"(c[2]), "+f"(c[3])
        : "r"(a[0]), "r"(a[1]), "r"(a[2]), "r"(a[3]), "r"(b[0]), "r"(b[1]));
}
__device__ __forceinline__ void cp16(uint32_t dst, const void* src) {
    asm volatile("cp.async.ca.shared.global [%0], [%1], 16;" :: "r"(dst), "l"(src));
}
__device__ __forceinline__ void cp16p(uint32_t dst, const void* src, int srcsize) {
    asm volatile("cp.async.ca.shared.global [%0], [%1], 16, %2;" :: "r"(dst), "l"(src), "r"(srcsize));
}
#define CP_COMMIT() asm volatile("cp.async.commit_group;" ::: "memory")
#define CP_WAIT1()  asm volatile("cp.async.wait_group 1;" ::: "memory")

__device__ __forceinline__ void splitf(float f, unsigned short& h, unsigned short& l) {
    __nv_bfloat16 bh = __float2bfloat16(f);
    float r = f - __bfloat162float(bh);
    __nv_bfloat16 bl = __float2bfloat16(r);
    h = reinterpret_cast<unsigned short&>(bh);
    l = reinterpret_cast<unsigned short&>(bl);
}
__device__ __forceinline__ void split4(float4 v, uint2& hi, uint2& lo) {
    unsigned short h0, h1, h2, h3, l0, l1, l2, l3;
    splitf(v.x, h0, l0); splitf(v.y, h1, l1);
    splitf(v.z, h2, l2); splitf(v.w, h3, l3);
    hi.x = (uint32_t)h0 | ((uint32_t)h1 << 16);
    hi.y = (uint32_t)h2 | ((uint32_t)h3 << 16);
    lo.x = (uint32_t)l0 | ((uint32_t)l1 << 16);
    lo.y = (uint32_t)l2 | ((uint32_t)l3 << 16);
}

// ================= split / split-add =======================================
__global__ void split_kernel(const float4* __restrict__ in, uint2* __restrict__ hi,
                             uint2* __restrict__ lo, int n4) {
    int i = blockIdx.x * blockDim.x + threadIdx.x;
    if (i < n4) { uint2 h, l; split4(in[i], h, l); hi[i] = h; lo[i] = l; }
}
__global__ void split_add_kernel(const float4* __restrict__ a, const float4* __restrict__ b,
                                 uint2* __restrict__ hi, uint2* __restrict__ lo, int n4) {
    int i = blockIdx.x * blockDim.x + threadIdx.x;
    if (i < n4) {
        float4 x = a[i], y = b[i];
        float4 s = make_float4(x.x + y.x, x.y + y.y, x.z + y.z, x.w + y.w);
        uint2 h, l; split4(s, h, l); hi[i] = h; lo[i] = l;
    }
}

// ================= bf16 HMMA GEMM with cp.async pipeline ===================
// C[M,N] = (Ah+Al)(Bh+Bl) + bias, NPROD=3: AhBh+AhBl+AlBh ; NPROD=1: AhBh
// OUT: 0 = fp32, 1 = fp16.
// Block 128x96x32, 8 warps (4m x 2n), warp tile 32x48, 3 stages.
#define BM 128
#define BN 96
#define BK 32
#define STAGES 3
#define SA 80
#define SB 208
#define A_BYTES (128*SA)          // 10240
#define B_BYTES (32*SB)           // 6656
#define OFF_AH 0
#define OFF_AL A_BYTES
#define OFF_BH (2*A_BYTES)
#define OFF_BL (2*A_BYTES + B_BYTES)
#define STAGE_SZ (2*A_BYTES + 2*B_BYTES)   // 33792
#define SMEM_TOT (STAGES*STAGE_SZ)         // 101376

template<int NPROD, int OUTF16>
__global__ __launch_bounds__(256, 2)
void gemm_bf16(const __nv_bfloat16* __restrict__ Ah, const __nv_bfloat16* __restrict__ Al,
               const __nv_bfloat16* __restrict__ Bh, const __nv_bfloat16* __restrict__ Bl,
               const float* __restrict__ bias, void* __restrict__ Cv,
               int M, int N, int K) {
    extern __shared__ char smem[];
    uint32_t sbase = smem_u32(smem);
    const int tid = threadIdx.x;
    const int lane = tid & 31, wid = tid >> 5;
    const int warp_m = wid & 3, warp_n = wid >> 2;
    const int bm = blockIdx.y * BM;
    const int bn = blockIdx.x * BN;
    const int nchunk = K / BK;

    auto load_chunk = [&](int c, int s) {
        const int k0 = c * BK;
        char* sb = smem + s * STAGE_SZ;
#pragma unroll
        for (int t = 0; t < 2; t++) {
            int idx = tid + t * 256, r = idx >> 2, c4 = idx & 3;
            uint32_t dst = smem_u32(sb + OFF_AH + r * SA + c4 * 16);
            cp16(dst, &Ah[(size_t)(bm + r) * K + k0 + c4 * 8]);
            if (NPROD == 3)
                cp16(dst + A_BYTES, &Al[(size_t)(bm + r) * K + k0 + c4 * 8]);
        }
#pragma unroll
        for (int t = 0; t < 2; t++) {
            int idx = tid + t * 256;
            if (idx < 384) {
                int r = idx / 12, g = idx % 12;
                int col = bn + g * 8;
                int sz = (col < N) ? 16 : 0;
                uint32_t dst = smem_u32(sb + OFF_BH + r * SB + g * 16);
                cp16p(dst, &Bh[(size_t)(k0 + r) * N + col], sz);
                if (NPROD == 3)
                    cp16p(dst + B_BYTES, &Bl[(size_t)(k0 + r) * N + col], sz);
            }
        }
    };

    float acc[2][6][4];
#pragma unroll
    for (int mi = 0; mi < 2; mi++)
#pragma unroll
        for (int ni = 0; ni < 6; ni++)
#pragma unroll
            for (int j = 0; j < 4; j++) acc[mi][ni][j] = 0.f;

    load_chunk(0, 0); CP_COMMIT();
    load_chunk(1, 1); CP_COMMIT();

    for (int c = 0; c < nchunk; c++) {
        CP_WAIT1();
        __syncthreads();
        if (c + 2 < nchunk) load_chunk(c + 2, (c + 2) % STAGES);
        CP_COMMIT();

        uint32_t sbuf = sbase + (c % STAGES) * STAGE_SZ;
#pragma unroll
        for (int ks = 0; ks < 2; ks++) {
            uint32_t a_hi[2][4], a_lo[2][4], b_hi[6][2], b_lo[6][2];
#pragma unroll
            for (int mi = 0; mi < 2; mi++) {
                uint32_t ad = sbuf + OFF_AH
                    + (warp_m * 32 + mi * 16 + (lane & 15)) * SA
                    + ks * 32 + (lane >> 4) * 16;
                ldsm_x4(a_hi[mi], ad);
                if (NPROD == 3) ldsm_x4(a_lo[mi], ad + A_BYTES);
            }
#pragma unroll
            for (int nt = 0; nt < 3; nt++) {
                uint32_t bd = sbuf + OFF_BH
                    + (ks * 16 + (lane & 15)) * SB
                    + (warp_n * 48 + nt * 16) * 2 + (lane >> 4) * 16;
                uint32_t r[4];
                ldsm_x4_t(r, bd);
                b_hi[nt * 2][0] = r[0]; b_hi[nt * 2][1] = r[1];
                b_hi[nt * 2 + 1][0] = r[2]; b_hi[nt * 2 + 1][1] = r[3];
                if (NPROD == 3) {
                    ldsm_x4_t(r, bd + B_BYTES);
                    b_lo[nt * 2][0] = r[0]; b_lo[nt * 2][1] = r[1];
                    b_lo[nt * 2 + 1][0] = r[2]; b_lo[nt * 2 + 1][1] = r[3];
                }
            }
#pragma unroll
            for (int mi = 0; mi < 2; mi++)
#pragma unroll
                for (int ni = 0; ni < 6; ni++) {
                    mma_bf16(acc[mi][ni], a_hi[mi], b_hi[ni]);
                    if (NPROD == 3) {
                        mma_bf16(acc[mi][ni], a_hi[mi], b_lo[ni]);
                        mma_bf16(acc[mi][ni], a_lo[mi], b_hi[ni]);
                    }
                }
        }
        __syncthreads();
    }

    // ---- epilogue ----
    const int row_base = bm + warp_m * 32 + (lane >> 2);
    const int col_base = bn + warp_n * 48 + (lane & 3) * 2;
#pragma unroll
    for (int mi = 0; mi < 2; mi++)
#pragma unroll
        for (int r2 = 0; r2 < 2; r2++) {
            int row = row_base + mi * 16 + r2 * 8;
#pragma unroll
            for (int ni = 0; ni < 6; ni++) {
                int col = col_base + ni * 8;
                if (col < N) {
                    float ox = acc[mi][ni][r2 * 2 + 0] + bias[col];
                    float oy = acc[mi][ni][r2 * 2 + 1] + bias[col + 1];
                    if (OUTF16) {
                        __half2 pk = __floats2half2_rn(ox, oy);
                        *reinterpret_cast<__half2*>(
                            &((__half*)Cv)[(size_t)row * N + col]) = pk;
                    } else {
                        float2 o; o.x = ox; o.y = oy;
                        *reinterpret_cast<float2*>(&((float*)Cv)[(size_t)row * N + col]) = o;
                    }
                }
            }
        }
}

// ================= deformable 3D trilinear sampling (fp16 v) ===============
__global__ __launch_bounds__(256)
void deform_sample(const __half* __restrict__ v, const float* __restrict__ offs,
                   const float* __restrict__ lg,
                   __nv_bfloat16* __restrict__ oh, __nv_bfloat16* __restrict__ ol) {
    int wg = (blockIdx.x * blockDim.x + threadIdx.x) >> 5;
    int lane = threadIdx.x & 31;
    const int total = BSZ * HEADS * NQ;
    if (wg >= total) return;

    int q    = wg % NQ;
    int head = (wg / NQ) % HEADS;
    int b    = wg / (NQ * HEADS);

    int qx = q % WW;
    int qy = q / WW;
    float refx = ((float)qx + 0.5f) / (float)WW;
    float refy = ((float)qy + 0.5f) / (float)HH;

    const float* lgp = lg + (((size_t)b * NQ + q) * HEADS + head) * NPTS;
    float wt[NPTS];
    float mx = -1e30f;
#pragma unroll
    for (int p = 0; p < NPTS; p++) mx = fmaxf(mx, lgp[p]);
    float s = 0.f;
#pragma unroll
    for (int p = 0; p < NPTS; p++) { wt[p] = expf(lgp[p] - mx); s += wt[p]; }
    float invs = 1.f / s;

    const float* offp = offs + ((((size_t)b * NQ + q) * HEADS + head) * NPTS) * 3;
    const __half* vbh = v + (size_t)b * NV * EE + head * HD + lane;

    float acc = 0.f;
#pragma unroll
    for (int p = 0; p < NPTS; p++) {
        float ox = offp[p * 3 + 0];
        float oy = offp[p * 3 + 1];
        float oz = offp[p * 3 + 2];
        float x = (refx + ox / (float)WW) * (float)WW - 0.5f;
        float y = (refy + oy / (float)HH) * (float)HH - 0.5f;
        float z = (oz / (float)NFR) * (float)DDEP - 0.5f;
        float x0f = floorf(x), y0f = floorf(y), z0f = floorf(z);
        float fx = x - x0f, fy = y - y0f, fz = z - z0f;
        int ix0 = (int)x0f, iy0 = (int)y0f, iz0 = (int)z0f;
        float ap = wt[p] * invs;
#pragma unroll
        for (int dz = 0; dz < 2; dz++) {
            int zi = iz0 + dz;
            if ((unsigned)zi >= DDEP) continue;
            float wz = dz ? fz : (1.f - fz);
#pragma unroll
            for (int dy = 0; dy < 2; dy++) {
                int yi = iy0 + dy;
                if ((unsigned)yi >= HH) continue;
                float wzy = wz * (dy ? fy : (1.f - fy));
#pragma unroll
                for (int dx = 0; dx < 2; dx++) {
                    int xi = ix0 + dx;
                    if ((unsigned)xi >= WW) continue;
                    float wgt = wzy * (dx ? fx : (1.f - fx));
                    int idx = (zi * HH + yi) * WW + xi;
                    acc += ap * wgt * __half2float(__ldg(&vbh[(size_t)idx * EE]));
                }
            }
        }
    }
    unsigned short h, l;
    splitf(acc, h, l);
    size_t oidx = ((size_t)b * NQ + q) * EE + head * HD + lane;
    oh[oidx] = reinterpret_cast<__nv_bfloat16&>(h);
    ol[oidx] = reinterpret_cast<__nv_bfloat16&>(l);
}

// ================= launch ==================================================
extern "C" void kernel_launch(void* const* d_in, const int* in_sizes, int n_in,
                              void* d_out, int out_size) {
    const float* query  = (const float*)d_in[0];
    const float* value  = (const float*)d_in[1];
    const float* qpos   = (const float*)d_in[2];
    const float* W_off  = (const float*)d_in[3];
    const float* b_off  = (const float*)d_in[4];
    const float* W_attn = (const float*)d_in[5];
    const float* b_attn = (const float*)d_in[6];
    const float* W_v    = (const float*)d_in[7];
    const float* b_v    = (const float*)d_in[8];
    const float* W_out  = (const float*)d_in[9];
    const float* b_out  = (const float*)d_in[10];
    float* out = (float*)d_out;

    float *offs_s, *attn_s;
    __half *vf;
    __nv_bfloat16 *vh, *vl, *qh, *ql, *sph, *spl;
    __nv_bfloat16 *wvh, *wvl, *woh, *wol, *wah, *wal, *wuh, *wul;
    cudaGetSymbolAddress((void**)&offs_s, g_offs);
    cudaGetSymbolAddress((void**)&attn_s, g_attn);
    cudaGetSymbolAddress((void**)&vf,  g_vf);
    cudaGetSymbolAddress((void**)&vh,  g_vh);  cudaGetSymbolAddress((void**)&vl,  g_vl);
    cudaGetSymbolAddress((void**)&qh,  g_qh);  cudaGetSymbolAddress((void**)&ql,  g_ql);
    cudaGetSymbolAddress((void**)&sph, g_sph); cudaGetSymbolAddress((void**)&spl, g_spl);
    cudaGetSymbolAddress((void**)&wvh, g_wvh); cudaGetSymbolAddress((void**)&wvl, g_wvl);
    cudaGetSymbolAddress((void**)&woh, g_woh); cudaGetSymbolAddress((void**)&wol, g_wol);
    cudaGetSymbolAddress((void**)&wah, g_wah); cudaGetSymbolAddress((void**)&wal, g_wal);
    cudaGetSymbolAddress((void**)&wuh, g_wuh); cudaGetSymbolAddress((void**)&wul, g_wul);

    static int smem_set = 0;
    if (!smem_set) {
        cudaFuncSetAttribute(gemm_bf16<3,0>, cudaFuncAttributeMaxDynamicSharedMemorySize, SMEM_TOT);
        cudaFuncSetAttribute(gemm_bf16<3,1>, cudaFuncAttributeMaxDynamicSharedMemorySize, SMEM_TOT);
        cudaFuncSetAttribute(gemm_bf16<1,0>, cudaFuncAttributeMaxDynamicSharedMemorySize, SMEM_TOT);
        smem_set = 1;
    }

    // 1) splits
    {
        int n4 = (BSZ * NQ * EE) / 4;
        split_add_kernel<<<(n4 + 255) / 256, 256>>>(
            (const float4*)query, (const float4*)qpos, (uint2*)qh, (uint2*)ql, n4);
    }
    {
        int n4 = (BSZ * NV * EE) / 4;
        split_kernel<<<(n4 + 255) / 256, 256>>>((const float4*)value, (uint2*)vh, (uint2*)vl, n4);
    }
    {
        int n4 = (EE * EE) / 4;
        split_kernel<<<(n4 + 255) / 256, 256>>>((const float4*)W_v, (uint2*)wvh, (uint2*)wvl, n4);
        split_kernel<<<(n4 + 255) / 256, 256>>>((const float4*)W_out, (uint2*)wuh, (uint2*)wul, n4);
        int n4o = (EE * NOFF) / 4;
        split_kernel<<<(n4o + 255) / 256, 256>>>((const float4*)W_off, (uint2*)woh, (uint2*)wol, n4o);
        int n4a = (EE * NATT) / 4;
        split_kernel<<<(n4a + 255) / 256, 256>>>((const float4*)W_attn, (uint2*)wah, (uint2*)wal, n4a);
    }
    // 2) v = value @ W_v + b_v   (M=51200, N=576) -> fp16
    {
        dim3 grid(EE / BN, (BSZ * NV) / BM);
        gemm_bf16<3,1><<<grid, 256, SMEM_TOT>>>(vh, vl, wvh, wvl, b_v, vf, BSZ * NV, EE, EE);
    }
    // 3) offs = q @ W_off + b_off  (N=648)
    {
        dim3 grid((NOFF + BN - 1) / BN, (BSZ * NQ) / BM);
        gemm_bf16<1,0><<<grid, 256, SMEM_TOT>>>(qh, ql, woh, wol, b_off, offs_s, BSZ * NQ, NOFF, EE);
    }
    // 4) attn logits  (N=216)
    {
        dim3 grid((NATT + BN - 1) / BN, (BSZ * NQ) / BM);
        gemm_bf16<1,0><<<grid, 256, SMEM_TOT>>>(qh, ql, wah, wal, b_attn, attn_s, BSZ * NQ, NATT, EE);
    }
    // 5) trilinear sampling + softmax weighting -> bf16 hi/lo
    {
        int warps = BSZ * HEADS * NQ;
        int blocks = (warps + 7) / 8;
        deform_sample<<<blocks, 256>>>(vf, offs_s, attn_s, sph, spl);
    }
    // 6) out = samp @ W_out + b_out  (N=576)
    {
        dim3 grid(EE / BN, (BSZ * NQ) / BM);
        gemm_bf16<3,0><<<grid, 256, SMEM_TOT>>>(sph, spl, wuh, wul, b_out, out, BSZ * NQ, EE, EE);
    }
}

// round 9
// speedup vs baseline: 1.1185x; 1.1185x over previous
#include <cuda_runtime.h>
#include <cuda_fp16.h>
#include <cstdint>
#include <math.h>

#define BSZ 2
#define HH 64
#define WW 80
#define NQ (HH*WW)          // 5120
#define EE 576
#define HEADS 18
#define HD 32
#define NPTS 12
#define NFR 3
#define DDEP 5
#define NV (NQ*DDEP)        // 25600
#define NOFF (HEADS*NPTS*3) // 648
#define NATT (HEADS*NPTS)   // 216

// ---------------- scratch (device globals; no allocation allowed) ----------
__device__ float g_offs[(size_t)BSZ*NQ*NOFF];
__device__ float g_attn[(size_t)BSZ*NQ*NATT];

__device__ __align__(128) __half g_vf  [(size_t)BSZ*NV*EE];   // projected v, fp16
__device__ __align__(128) __half g_vh  [(size_t)BSZ*NV*EE];
__device__ __align__(128) __half g_vl  [(size_t)BSZ*NV*EE];
__device__ __align__(128) __half g_qh  [(size_t)BSZ*NQ*EE];
__device__ __align__(128) __half g_ql  [(size_t)BSZ*NQ*EE];
__device__ __align__(128) __half g_sph [(size_t)BSZ*NQ*EE];
__device__ __align__(128) __half g_spl [(size_t)BSZ*NQ*EE];
__device__ __align__(128) __half g_wvh [(size_t)EE*EE];
__device__ __align__(128) __half g_wvl [(size_t)EE*EE];
__device__ __align__(128) __half g_woh [(size_t)EE*NOFF];
__device__ __align__(128) __half g_wol [(size_t)EE*NOFF];
__device__ __align__(128) __half g_wah [(size_t)EE*NATT];
__device__ __align__(128) __half g_wal [(size_t)EE*NATT];
__device__ __align__(128) __half g_wuh [(size_t)EE*EE];
__device__ __align__(128) __half g_wul [(size_t)EE*EE];

// ================= helpers =================================================
__device__ __forceinline__ uint32_t smem_u32(const void* p) {
    uint32_t a;
    asm("{ .reg .u64 t; cvta.to.shared.u64 t, %1; cvt.u32.u64 %0, t; }" : "=r"(a) : "l"(p));
    return a;
}
__device__ __forceinline__ void ldsm_x4(uint32_t* r, uint32_t addr) {
    asm volatile("ldmatrix.sync.aligned.m8n8.x4.shared.b16 {%0,%1,%2,%3}, [%4];"
                 : "=r"(r[0]), "=r"(r[1]), "=r"(r[2]), "=r"(r[3]) : "r"(addr));
}
__device__ __forceinline__ void ldsm_x4_t(uint32_t* r, uint32_t addr) {
    asm volatile("ldmatrix.sync.aligned.m8n8.x4.trans.shared.b16 {%0,%1,%2,%3}, [%4];"
                 : "=r"(r[0]), "=r"(r[1]), "=r"(r[2]), "=r"(r[3]) : "r"(addr));
}
__device__ __forceinline__ void mma_f16(float* c, const uint32_t* a, const uint32_t* b) {
    asm volatile(
        "mma.sync.aligned.m16n8k16.row.col.f32.f16.f16.f32 "
        "{%0,%1,%2,%3}, {%4,%5,%6,%7}, {%8,%9}, {%0,%1,%2,%3};"
        : "+f"(c[0]), "+f"(c[1]), "+f"(c[2]), "+f"(c[3])
        : "r"(a[0]), "r"(a[1]), "r"(a[2]), "r"(a[3]), "r"(b[0]), "r"(b[1]));
}
__device__ __forceinline__ void cp16(uint32_t dst, const void* src) {
    asm volatile("cp.async.ca.shared.global [%0], [%1], 16;" :: "r"(dst), "l"(src));
}
__device__ __forceinline__ void cp16p(uint32_t dst, const void* src, int srcsize) {
    asm volatile("cp.async.ca.shared.global [%0], [%1], 16, %2;" :: "r"(dst), "l"(src), "r"(srcsize));
}
#define CP_COMMIT() asm volatile("cp.async.commit_group;" ::: "memory")
#define CP_WAIT1()  asm volatile("cp.async.wait_group 1;" ::: "memory")

__device__ __forceinline__ void splith(float f, unsigned short& h, unsigned short& l) {
    __half hh = __float2half_rn(f);
    float r = f - __half2float(hh);
    __half hl = __float2half_rn(r);
    h = reinterpret_cast<unsigned short&>(hh);
    l = reinterpret_cast<unsigned short&>(hl);
}
__device__ __forceinline__ void split4(float4 v, uint2& hi, uint2& lo) {
    unsigned short h0, h1, h2, h3, l0, l1, l2, l3;
    splith(v.x, h0, l0); splith(v.y, h1, l1);
    splith(v.z, h2, l2); splith(v.w, h3, l3);
    hi.x = (uint32_t)h0 | ((uint32_t)h1 << 16);
    hi.y = (uint32_t)h2 | ((uint32_t)h3 << 16);
    lo.x = (uint32_t)l0 | ((uint32_t)l1 << 16);
    lo.y = (uint32_t)l2 | ((uint32_t)l3 << 16);
}

// ================= split / split-add =======================================
__global__ void split_kernel(const float4* __restrict__ in, uint2* __restrict__ hi,
                             uint2* __restrict__ lo, int n4) {
    int i = blockIdx.x * blockDim.x + threadIdx.x;
    if (i < n4) { uint2 h, l; split4(in[i], h, l); hi[i] = h; lo[i] = l; }
}
__global__ void split_add_kernel(const float4* __restrict__ a, const float4* __restrict__ b,
                                 uint2* __restrict__ hi, uint2* __restrict__ lo, int n4) {
    int i = blockIdx.x * blockDim.x + threadIdx.x;
    if (i < n4) {
        float4 x = a[i], y = b[i];
        float4 s = make_float4(x.x + y.x, x.y + y.y, x.z + y.z, x.w + y.w);
        uint2 h, l; split4(s, h, l); hi[i] = h; lo[i] = l;
    }
}

// ================= fp16 HMMA GEMM with cp.async pipeline ===================
// NPROD=1: AhBh ; NPROD=2: AhBh+AlBh ; NPROD=3: AhBh+AlBh+AhBl
// OUTF16: 0 = fp32 output, 1 = fp16 output.
// Block 128x96x32, 8 warps (4m x 2n), warp tile 32x48, 3 stages.
#define BM 128
#define BN 96
#define BK 32
#define STAGES 3
#define SA 80
#define SB 208
#define A_BYTES (128*SA)          // 10240
#define B_BYTES (32*SB)           // 6656
#define OFF_AH 0
#define OFF_AL A_BYTES
#define OFF_BH (2*A_BYTES)
#define OFF_BL (2*A_BYTES + B_BYTES)
#define STAGE_SZ (2*A_BYTES + 2*B_BYTES)   // 33792
#define SMEM_TOT (STAGES*STAGE_SZ)         // 101376

template<int NPROD, int OUTF16>
__global__ __launch_bounds__(256, 2)
void gemm_f16(const __half* __restrict__ Ah, const __half* __restrict__ Al,
              const __half* __restrict__ Bh, const __half* __restrict__ Bl,
              const float* __restrict__ bias, void* __restrict__ Cv,
              int M, int N, int K) {
    extern __shared__ char smem[];
    uint32_t sbase = smem_u32(smem);
    const int tid = threadIdx.x;
    const int lane = tid & 31, wid = tid >> 5;
    const int warp_m = wid & 3, warp_n = wid >> 2;
    const int bm = blockIdx.y * BM;
    const int bn = blockIdx.x * BN;
    const int nchunk = K / BK;

    auto load_chunk = [&](int c, int s) {
        const int k0 = c * BK;
        char* sb = smem + s * STAGE_SZ;
#pragma unroll
        for (int t = 0; t < 2; t++) {
            int idx = tid + t * 256, r = idx >> 2, c4 = idx & 3;
            uint32_t dst = smem_u32(sb + OFF_AH + r * SA + c4 * 16);
            cp16(dst, &Ah[(size_t)(bm + r) * K + k0 + c4 * 8]);
            if (NPROD >= 2)
                cp16(dst + A_BYTES, &Al[(size_t)(bm + r) * K + k0 + c4 * 8]);
        }
#pragma unroll
        for (int t = 0; t < 2; t++) {
            int idx = tid + t * 256;
            if (idx < 384) {
                int r = idx / 12, g = idx % 12;
                int col = bn + g * 8;
                int sz = (col < N) ? 16 : 0;
                uint32_t dst = smem_u32(sb + OFF_BH + r * SB + g * 16);
                cp16p(dst, &Bh[(size_t)(k0 + r) * N + col], sz);
                if (NPROD >= 3)
                    cp16p(dst + B_BYTES, &Bl[(size_t)(k0 + r) * N + col], sz);
            }
        }
    };

    float acc[2][6][4];
#pragma unroll
    for (int mi = 0; mi < 2; mi++)
#pragma unroll
        for (int ni = 0; ni < 6; ni++)
#pragma unroll
            for (int j = 0; j < 4; j++) acc[mi][ni][j] = 0.f;

    load_chunk(0, 0); CP_COMMIT();
    load_chunk(1, 1); CP_COMMIT();

    for (int c = 0; c < nchunk; c++) {
        CP_WAIT1();
        __syncthreads();
        if (c + 2 < nchunk) load_chunk(c + 2, (c + 2) % STAGES);
        CP_COMMIT();

        uint32_t sbuf = sbase + (c % STAGES) * STAGE_SZ;
#pragma unroll
        for (int ks = 0; ks < 2; ks++) {
            uint32_t a_hi[2][4], a_lo[2][4], b_hi[6][2], b_lo[6][2];
#pragma unroll
            for (int mi = 0; mi < 2; mi++) {
                uint32_t ad = sbuf + OFF_AH
                    + (warp_m * 32 + mi * 16 + (lane & 15)) * SA
                    + ks * 32 + (lane >> 4) * 16;
                ldsm_x4(a_hi[mi], ad);
                if (NPROD >= 2) ldsm_x4(a_lo[mi], ad + A_BYTES);
            }
#pragma unroll
            for (int nt = 0; nt < 3; nt++) {
                uint32_t bd = sbuf + OFF_BH
                    + (ks * 16 + (lane & 15)) * SB
                    + (warp_n * 48 + nt * 16) * 2 + (lane >> 4) * 16;
                uint32_t r[4];
                ldsm_x4_t(r, bd);
                b_hi[nt * 2][0] = r[0]; b_hi[nt * 2][1] = r[1];
                b_hi[nt * 2 + 1][0] = r[2]; b_hi[nt * 2 + 1][1] = r[3];
                if (NPROD >= 3) {
                    ldsm_x4_t(r, bd + B_BYTES);
                    b_lo[nt * 2][0] = r[0]; b_lo[nt * 2][1] = r[1];
                    b_lo[nt * 2 + 1][0] = r[2]; b_lo[nt * 2 + 1][1] = r[3];
                }
            }
#pragma unroll
            for (int mi = 0; mi < 2; mi++)
#pragma unroll
                for (int ni = 0; ni < 6; ni++) {
                    mma_f16(acc[mi][ni], a_hi[mi], b_hi[ni]);
                    if (NPROD >= 2) mma_f16(acc[mi][ni], a_lo[mi], b_hi[ni]);
                    if (NPROD >= 3) mma_f16(acc[mi][ni], a_hi[mi], b_lo[ni]);
                }
        }
        __syncthreads();
    }

    // ---- epilogue ----
    const int row_base = bm + warp_m * 32 + (lane >> 2);
    const int col_base = bn + warp_n * 48 + (lane & 3) * 2;
#pragma unroll
    for (int mi = 0; mi < 2; mi++)
#pragma unroll
        for (int r2 = 0; r2 < 2; r2++) {
            int row = row_base + mi * 16 + r2 * 8;
#pragma unroll
            for (int ni = 0; ni < 6; ni++) {
                int col = col_base + ni * 8;
                if (col < N) {
                    float ox = acc[mi][ni][r2 * 2 + 0] + bias[col];
                    float oy = acc[mi][ni][r2 * 2 + 1] + bias[col + 1];
                    if (OUTF16) {
                        __half2 pk = __floats2half2_rn(ox, oy);
                        *reinterpret_cast<__half2*>(
                            &((__half*)Cv)[(size_t)row * N + col]) = pk;
                    } else {
                        float2 o; o.x = ox; o.y = oy;
                        *reinterpret_cast<float2*>(&((float*)Cv)[(size_t)row * N + col]) = o;
                    }
                }
            }
        }
}

// ================= deformable 3D trilinear sampling (fp16 v) ===============
__global__ __launch_bounds__(256)
void deform_sample(const __half* __restrict__ v, const float* __restrict__ offs,
                   const float* __restrict__ lg,
                   __half* __restrict__ oh, __half* __restrict__ ol) {
    int wg = (blockIdx.x * blockDim.x + threadIdx.x) >> 5;
    int lane = threadIdx.x & 31;
    const int total = BSZ * HEADS * NQ;
    if (wg >= total) return;

    int q    = wg % NQ;
    int head = (wg / NQ) % HEADS;
    int b    = wg / (NQ * HEADS);

    int qx = q % WW;
    int qy = q / WW;
    float refx = ((float)qx + 0.5f) / (float)WW;
    float refy = ((float)qy + 0.5f) / (float)HH;

    const float* lgp = lg + (((size_t)b * NQ + q) * HEADS + head) * NPTS;
    float wt[NPTS];
    float mx = -1e30f;
#pragma unroll
    for (int p = 0; p < NPTS; p++) mx = fmaxf(mx, lgp[p]);
    float s = 0.f;
#pragma unroll
    for (int p = 0; p < NPTS; p++) { wt[p] = expf(lgp[p] - mx); s += wt[p]; }
    float invs = 1.f / s;

    const float* offp = offs + ((((size_t)b * NQ + q) * HEADS + head) * NPTS) * 3;
    const __half* vbh = v + (size_t)b * NV * EE + head * HD + lane;

    float acc = 0.f;
#pragma unroll
    for (int p = 0; p < NPTS; p++) {
        float ox = offp[p * 3 + 0];
        float oy = offp[p * 3 + 1];
        float oz = offp[p * 3 + 2];
        float x = (refx + ox / (float)WW) * (float)WW - 0.5f;
        float y = (refy + oy / (float)HH) * (float)HH - 0.5f;
        float z = (oz / (float)NFR) * (float)DDEP - 0.5f;
        float x0f = floorf(x), y0f = floorf(y), z0f = floorf(z);
        float fx = x - x0f, fy = y - y0f, fz = z - z0f;
        int ix0 = (int)x0f, iy0 = (int)y0f, iz0 = (int)z0f;
        float ap = wt[p] * invs;
#pragma unroll
        for (int dz = 0; dz < 2; dz++) {
            int zi = iz0 + dz;
            if ((unsigned)zi >= DDEP) continue;
            float wz = dz ? fz : (1.f - fz);
#pragma unroll
            for (int dy = 0; dy < 2; dy++) {
                int yi = iy0 + dy;
                if ((unsigned)yi >= HH) continue;
                float wzy = wz * (dy ? fy : (1.f - fy));
#pragma unroll
                for (int dx = 0; dx < 2; dx++) {
                    int xi = ix0 + dx;
                    if ((unsigned)xi >= WW) continue;
                    float wgt = wzy * (dx ? fx : (1.f - fx));
                    int idx = (zi * HH + yi) * WW + xi;
                    acc += ap * wgt * __half2float(__ldg(&vbh[(size_t)idx * EE]));
                }
            }
        }
    }
    unsigned short h, l;
    splith(acc, h, l);
    size_t oidx = ((size_t)b * NQ + q) * EE + head * HD + lane;
    oh[oidx] = reinterpret_cast<__half&>(h);
    ol[oidx] = reinterpret_cast<__half&>(l);
}

// ================= launch ==================================================
extern "C" void kernel_launch(void* const* d_in, const int* in_sizes, int n_in,
                              void* d_out, int out_size) {
    const float* query  = (const float*)d_in[0];
    const float* value  = (const float*)d_in[1];
    const float* qpos   = (const float*)d_in[2];
    const float* W_off  = (const float*)d_in[3];
    const float* b_off  = (const float*)d_in[4];
    const float* W_attn = (const float*)d_in[5];
    const float* b_attn = (const float*)d_in[6];
    const float* W_v    = (const float*)d_in[7];
    const float* b_v    = (const float*)d_in[8];
    const float* W_out  = (const float*)d_in[9];
    const float* b_out  = (const float*)d_in[10];
    float* out = (float*)d_out;

    float *offs_s, *attn_s;
    __half *vf, *vh, *vl, *qh, *ql, *sph, *spl;
    __half *wvh, *wvl, *woh, *wol, *wah, *wal, *wuh, *wul;
    cudaGetSymbolAddress((void**)&offs_s, g_offs);
    cudaGetSymbolAddress((void**)&attn_s, g_attn);
    cudaGetSymbolAddress((void**)&vf,  g_vf);
    cudaGetSymbolAddress((void**)&vh,  g_vh);  cudaGetSymbolAddress((void**)&vl,  g_vl);
    cudaGetSymbolAddress((void**)&qh,  g_qh);  cudaGetSymbolAddress((void**)&ql,  g_ql);
    cudaGetSymbolAddress((void**)&sph, g_sph); cudaGetSymbolAddress((void**)&spl, g_spl);
    cudaGetSymbolAddress((void**)&wvh, g_wvh); cudaGetSymbolAddress((void**)&wvl, g_wvl);
    cudaGetSymbolAddress((void**)&woh, g_woh); cudaGetSymbolAddress((void**)&wol, g_wol);
    cudaGetSymbolAddress((void**)&wah, g_wah); cudaGetSymbolAddress((void**)&wal, g_wal);
    cudaGetSymbolAddress((void**)&wuh, g_wuh); cudaGetSymbolAddress((void**)&wul, g_wul);

    static int smem_set = 0;
    if (!smem_set) {
        cudaFuncSetAttribute(gemm_f16<3,0>, cudaFuncAttributeMaxDynamicSharedMemorySize, SMEM_TOT);
        cudaFuncSetAttribute(gemm_f16<2,1>, cudaFuncAttributeMaxDynamicSharedMemorySize, SMEM_TOT);
        cudaFuncSetAttribute(gemm_f16<1,0>, cudaFuncAttributeMaxDynamicSharedMemorySize, SMEM_TOT);
        smem_set = 1;
    }

    // Launch order arranged so ncu (-s 5 -c 1) profiles the value GEMM (6th).
    // 1-4) weight splits
    {
        int n4 = (EE * EE) / 4;
        split_kernel<<<(n4 + 255) / 256, 256>>>((const float4*)W_v, (uint2*)wvh, (uint2*)wvl, n4);
        split_kernel<<<(n4 + 255) / 256, 256>>>((const float4*)W_out, (uint2*)wuh, (uint2*)wul, n4);
        int n4o = (EE * NOFF) / 4;
        split_kernel<<<(n4o + 255) / 256, 256>>>((const float4*)W_off, (uint2*)woh, (uint2*)wol, n4o);
        int n4a = (EE * NATT) / 4;
        split_kernel<<<(n4a + 255) / 256, 256>>>((const float4*)W_attn, (uint2*)wah, (uint2*)wal, n4a);
    }
    // 5) split value
    {
        int n4 = (BSZ * NV * EE) / 4;
        split_kernel<<<(n4 + 255) / 256, 256>>>((const float4*)value, (uint2*)vh, (uint2*)vl, n4);
    }
    // 6) v = value @ W_v + b_v   (M=51200, N=576) -> fp16, 2-product
    {
        dim3 grid(EE / BN, (BSZ * NV) / BM);
        gemm_f16<2,1><<<grid, 256, SMEM_TOT>>>(vh, vl, wvh, wvl, b_v, vf, BSZ * NV, EE, EE);
    }
    // 7) q = query + query_pos (split)
    {
        int n4 = (BSZ * NQ * EE) / 4;
        split_add_kernel<<<(n4 + 255) / 256, 256>>>(
            (const float4*)query, (const float4*)qpos, (uint2*)qh, (uint2*)ql, n4);
    }
    // 8) offs = q @ W_off + b_off  (N=648)
    {
        dim3 grid((NOFF + BN - 1) / BN, (BSZ * NQ) / BM);
        gemm_f16<1,0><<<grid, 256, SMEM_TOT>>>(qh, ql, woh, wol, b_off, offs_s, BSZ * NQ, NOFF, EE);
    }
    // 9) attn logits  (N=216)
    {
        dim3 grid((NATT + BN - 1) / BN, (BSZ * NQ) / BM);
        gemm_f16<1,0><<<grid, 256, SMEM_TOT>>>(qh, ql, wah, wal, b_attn, attn_s, BSZ * NQ, NATT, EE);
    }
    // 10) trilinear sampling + softmax weighting -> fp16 hi/lo
    {
        int warps = BSZ * HEADS * NQ;
        int blocks = (warps + 7) / 8;
        deform_sample<<<blocks, 256>>>(vf, offs_s, attn_s, sph, spl);
    }
    // 11) out = samp @ W_out + b_out  (N=576), 3-product
    {
        dim3 grid(EE / BN, (BSZ * NQ) / BM);
        gemm_f16<3,0><<<grid, 256, SMEM_TOT>>>(sph, spl, wuh, wul, b_out, out, BSZ * NQ, EE, EE);
    }
}

// round 10
// speedup vs baseline: 1.3525x; 1.2092x over previous
#include <cuda_runtime.h>
#include <cuda_fp16.h>
#include <cstdint>
#include <math.h>

#define BSZ 2
#define HH 64
#define WW 80
#define NQ (HH*WW)          // 5120
#define EE 576
#define HEADS 18
#define HD 32
#define NPTS 12
#define NFR 3
#define DDEP 5
#define NV (NQ*DDEP)        // 25600
#define NOFF (HEADS*NPTS*3) // 648
#define NATT (HEADS*NPTS)   // 216
#define NOA  (NOFF+NATT)    // 864  (combined offs|attn output width)

// ---------------- scratch (device globals; no allocation allowed) ----------
__device__ float g_oa  [(size_t)BSZ*NQ*NOA];    // combined offs(0..647)|attn(648..863)
__device__ float g_boa [NOA];                   // combined bias

__device__ __align__(128) __half g_vf  [(size_t)BSZ*NV*EE];   // projected v, fp16
__device__ __align__(128) __half g_vh  [(size_t)BSZ*NV*EE];   // value hi
__device__ __align__(128) __half g_qh  [(size_t)BSZ*NQ*EE];   // q hi
__device__ __align__(128) __half g_sph [(size_t)BSZ*NQ*EE];   // samp hi
__device__ __align__(128) __half g_spl [(size_t)BSZ*NQ*EE];   // samp lo
__device__ __align__(128) __half g_wvh [(size_t)EE*EE];       // W_v hi
__device__ __align__(128) __half g_woa [(size_t)EE*NOA];      // W_off|W_attn hi, combined
__device__ __align__(128) __half g_wuh [(size_t)EE*EE];       // W_out hi

// ================= helpers =================================================
__device__ __forceinline__ uint32_t smem_u32(const void* p) {
    uint32_t a;
    asm("{ .reg .u64 t; cvta.to.shared.u64 t, %1; cvt.u32.u64 %0, t; }" : "=r"(a) : "l"(p));
    return a;
}
__device__ __forceinline__ void ldsm_x4(uint32_t* r, uint32_t addr) {
    asm volatile("ldmatrix.sync.aligned.m8n8.x4.shared.b16 {%0,%1,%2,%3}, [%4];"
                 : "=r"(r[0]), "=r"(r[1]), "=r"(r[2]), "=r"(r[3]) : "r"(addr));
}
__device__ __forceinline__ void ldsm_x4_t(uint32_t* r, uint32_t addr) {
    asm volatile("ldmatrix.sync.aligned.m8n8.x4.trans.shared.b16 {%0,%1,%2,%3}, [%4];"
                 : "=r"(r[0]), "=r"(r[1]), "=r"(r[2]), "=r"(r[3]) : "r"(addr));
}
__device__ __forceinline__ void mma_f16(float* c, const uint32_t* a, const uint32_t* b) {
    asm volatile(
        "mma.sync.aligned.m16n8k16.row.col.f32.f16.f16.f32 "
        "{%0,%1,%2,%3}, {%4,%5,%6,%7}, {%8,%9}, {%0,%1,%2,%3};"
        : "+f"(c[0]), "+f"(c[1]), "+f"(c[2]), "+f"(c[3])
        : "r"(a[0]), "r"(a[1]), "r"(a[2]), "r"(a[3]), "r"(b[0]), "r"(b[1]));
}
__device__ __forceinline__ void cp16(uint32_t dst, const void* src) {
    asm volatile("cp.async.ca.shared.global [%0], [%1], 16;" :: "r"(dst), "l"(src));
}
__device__ __forceinline__ void cp16p(uint32_t dst, const void* src, int srcsize) {
    asm volatile("cp.async.ca.shared.global [%0], [%1], 16, %2;" :: "r"(dst), "l"(src), "r"(srcsize));
}
#define CP_COMMIT() asm volatile("cp.async.commit_group;" ::: "memory")
#define CP_WAIT1()  asm volatile("cp.async.wait_group 1;" ::: "memory")

__device__ __forceinline__ void splith(float f, unsigned short& h, unsigned short& l) {
    __half hh = __float2half_rn(f);
    float r = f - __half2float(hh);
    __half hl = __float2half_rn(r);
    h = reinterpret_cast<unsigned short&>(hh);
    l = reinterpret_cast<unsigned short&>(hl);
}
__device__ __forceinline__ uint2 hi4(float4 v) {
    __half2 a = __floats2half2_rn(v.x, v.y);
    __half2 b = __floats2half2_rn(v.z, v.w);
    uint2 r;
    r.x = reinterpret_cast<uint32_t&>(a);
    r.y = reinterpret_cast<uint32_t&>(b);
    return r;
}

// ================= conversion kernels ======================================
// hi-only split
__global__ void split1_kernel(const float4* __restrict__ in, uint2* __restrict__ hi, int n4) {
    int i = blockIdx.x * blockDim.x + threadIdx.x;
    if (i < n4) hi[i] = hi4(in[i]);
}
// q = a + b, hi only
__global__ void split_add1_kernel(const float4* __restrict__ a, const float4* __restrict__ b,
                                  uint2* __restrict__ hi, int n4) {
    int i = blockIdx.x * blockDim.x + threadIdx.x;
    if (i < n4) {
        float4 x = a[i], y = b[i];
        hi[i] = hi4(make_float4(x.x + y.x, x.y + y.y, x.z + y.z, x.w + y.w));
    }
}
// strided hi-only split into combined weight buffer (row stride NOA, col offset)
__global__ void split1_strided(const float* __restrict__ in, __half* __restrict__ out,
                               int K, int N, int coloff) {
    int i = blockIdx.x * blockDim.x + threadIdx.x;
    if (i < K * N) {
        int k = i / N, n = i % N;
        out[(size_t)k * NOA + coloff + n] = __float2half_rn(in[i]);
    }
}
__global__ void combine_bias(const float* __restrict__ b_off, const float* __restrict__ b_attn,
                             float* __restrict__ boa) {
    int i = blockIdx.x * blockDim.x + threadIdx.x;
    if (i < NOA) boa[i] = (i < NOFF) ? b_off[i] : b_attn[i - NOFF];
}

// ================= fp16 HMMA GEMM with cp.async pipeline ===================
// NPROD=1: AhBh ; NPROD=2: AhBh+AlBh ; NPROD=3: +AhBl
// OUTF16: 0 = fp32 output, 1 = fp16 output.
// Block 128x96x32, 8 warps (4m x 2n), warp tile 32x48, 3 stages.
#define BM 128
#define BN 96
#define BK 32
#define STAGES 3
#define SA 80
#define SB 208
#define A_BYTES (128*SA)          // 10240
#define B_BYTES (32*SB)           // 6656
#define OFF_AH 0
#define OFF_AL A_BYTES
#define OFF_BH (2*A_BYTES)
#define OFF_BL (2*A_BYTES + B_BYTES)
#define STAGE_SZ (2*A_BYTES + 2*B_BYTES)   // 33792
#define SMEM_TOT (STAGES*STAGE_SZ)         // 101376

template<int NPROD, int OUTF16>
__global__ __launch_bounds__(256, 2)
void gemm_f16(const __half* __restrict__ Ah, const __half* __restrict__ Al,
              const __half* __restrict__ Bh, const __half* __restrict__ Bl,
              const float* __restrict__ bias, void* __restrict__ Cv,
              int M, int N, int K) {
    extern __shared__ char smem[];
    uint32_t sbase = smem_u32(smem);
    const int tid = threadIdx.x;
    const int lane = tid & 31, wid = tid >> 5;
    const int warp_m = wid & 3, warp_n = wid >> 2;
    const int bm = blockIdx.y * BM;
    const int bn = blockIdx.x * BN;
    const int nchunk = K / BK;

    auto load_chunk = [&](int c, int s) {
        const int k0 = c * BK;
        char* sb = smem + s * STAGE_SZ;
#pragma unroll
        for (int t = 0; t < 2; t++) {
            int idx = tid + t * 256, r = idx >> 2, c4 = idx & 3;
            uint32_t dst = smem_u32(sb + OFF_AH + r * SA + c4 * 16);
            cp16(dst, &Ah[(size_t)(bm + r) * K + k0 + c4 * 8]);
            if (NPROD >= 2)
                cp16(dst + A_BYTES, &Al[(size_t)(bm + r) * K + k0 + c4 * 8]);
        }
#pragma unroll
        for (int t = 0; t < 2; t++) {
            int idx = tid + t * 256;
            if (idx < 384) {
                int r = idx / 12, g = idx % 12;
                int col = bn + g * 8;
                int sz = (col < N) ? 16 : 0;
                uint32_t dst = smem_u32(sb + OFF_BH + r * SB + g * 16);
                cp16p(dst, &Bh[(size_t)(k0 + r) * N + col], sz);
                if (NPROD >= 3)
                    cp16p(dst + B_BYTES, &Bl[(size_t)(k0 + r) * N + col], sz);
            }
        }
    };

    float acc[2][6][4];
#pragma unroll
    for (int mi = 0; mi < 2; mi++)
#pragma unroll
        for (int ni = 0; ni < 6; ni++)
#pragma unroll
            for (int j = 0; j < 4; j++) acc[mi][ni][j] = 0.f;

    load_chunk(0, 0); CP_COMMIT();
    load_chunk(1, 1); CP_COMMIT();

    for (int c = 0; c < nchunk; c++) {
        CP_WAIT1();
        __syncthreads();
        if (c + 2 < nchunk) load_chunk(c + 2, (c + 2) % STAGES);
        CP_COMMIT();

        uint32_t sbuf = sbase + (c % STAGES) * STAGE_SZ;
#pragma unroll
        for (int ks = 0; ks < 2; ks++) {
            uint32_t a_hi[2][4], a_lo[2][4], b_hi[6][2], b_lo[6][2];
#pragma unroll
            for (int mi = 0; mi < 2; mi++) {
                uint32_t ad = sbuf + OFF_AH
                    + (warp_m * 32 + mi * 16 + (lane & 15)) * SA
                    + ks * 32 + (lane >> 4) * 16;
                ldsm_x4(a_hi[mi], ad);
                if (NPROD >= 2) ldsm_x4(a_lo[mi], ad + A_BYTES);
            }
#pragma unroll
            for (int nt = 0; nt < 3; nt++) {
                uint32_t bd = sbuf + OFF_BH
                    + (ks * 16 + (lane & 15)) * SB
                    + (warp_n * 48 + nt * 16) * 2 + (lane >> 4) * 16;
                uint32_t r[4];
                ldsm_x4_t(r, bd);
                b_hi[nt * 2][0] = r[0]; b_hi[nt * 2][1] = r[1];
                b_hi[nt * 2 + 1][0] = r[2]; b_hi[nt * 2 + 1][1] = r[3];
                if (NPROD >= 3) {
                    ldsm_x4_t(r, bd + B_BYTES);
                    b_lo[nt * 2][0] = r[0]; b_lo[nt * 2][1] = r[1];
                    b_lo[nt * 2 + 1][0] = r[2]; b_lo[nt * 2 + 1][1] = r[3];
                }
            }
#pragma unroll
            for (int mi = 0; mi < 2; mi++)
#pragma unroll
                for (int ni = 0; ni < 6; ni++) {
                    mma_f16(acc[mi][ni], a_hi[mi], b_hi[ni]);
                    if (NPROD >= 2) mma_f16(acc[mi][ni], a_lo[mi], b_hi[ni]);
                    if (NPROD >= 3) mma_f16(acc[mi][ni], a_hi[mi], b_lo[ni]);
                }
        }
        __syncthreads();
    }

    // ---- epilogue ----
    const int row_base = bm + warp_m * 32 + (lane >> 2);
    const int col_base = bn + warp_n * 48 + (lane & 3) * 2;
#pragma unroll
    for (int mi = 0; mi < 2; mi++)
#pragma unroll
        for (int r2 = 0; r2 < 2; r2++) {
            int row = row_base + mi * 16 + r2 * 8;
#pragma unroll
            for (int ni = 0; ni < 6; ni++) {
                int col = col_base + ni * 8;
                if (col < N) {
                    float ox = acc[mi][ni][r2 * 2 + 0] + bias[col];
                    float oy = acc[mi][ni][r2 * 2 + 1] + bias[col + 1];
                    if (OUTF16) {
                        __half2 pk = __floats2half2_rn(ox, oy);
                        *reinterpret_cast<__half2*>(
                            &((__half*)Cv)[(size_t)row * N + col]) = pk;
                    } else {
                        float2 o; o.x = ox; o.y = oy;
                        *reinterpret_cast<float2*>(&((float*)Cv)[(size_t)row * N + col]) = o;
                    }
                }
            }
        }
}

// ================= deformable 3D trilinear sampling (fp16 v) ===============
// Reads offs + attn logits from combined [row][NOA] buffer.
__global__ __launch_bounds__(256)
void deform_sample(const __half* __restrict__ v, const float* __restrict__ oa,
                   __half* __restrict__ oh, __half* __restrict__ ol) {
    int wg = (blockIdx.x * blockDim.x + threadIdx.x) >> 5;
    int lane = threadIdx.x & 31;
    const int total = BSZ * HEADS * NQ;
    if (wg >= total) return;

    int q    = wg % NQ;
    int head = (wg / NQ) % HEADS;
    int b    = wg / (NQ * HEADS);
    size_t row = (size_t)b * NQ + q;

    int qx = q % WW;
    int qy = q / WW;
    float refx = ((float)qx + 0.5f) / (float)WW;
    float refy = ((float)qy + 0.5f) / (float)HH;

    const float* lgp = oa + row * NOA + NOFF + head * NPTS;
    float wt[NPTS];
    float mx = -1e30f;
#pragma unroll
    for (int p = 0; p < NPTS; p++) mx = fmaxf(mx, lgp[p]);
    float s = 0.f;
#pragma unroll
    for (int p = 0; p < NPTS; p++) { wt[p] = expf(lgp[p] - mx); s += wt[p]; }
    float invs = 1.f / s;

    const float* offp = oa + row * NOA + head * NPTS * 3;
    const __half* vbh = v + (size_t)b * NV * EE + head * HD + lane;

    float acc = 0.f;
#pragma unroll
    for (int p = 0; p < NPTS; p++) {
        float ox = offp[p * 3 + 0];
        float oy = offp[p * 3 + 1];
        float oz = offp[p * 3 + 2];
        float x = (refx + ox / (float)WW) * (float)WW - 0.5f;
        float y = (refy + oy / (float)HH) * (float)HH - 0.5f;
        float z = (oz / (float)NFR) * (float)DDEP - 0.5f;
        float x0f = floorf(x), y0f = floorf(y), z0f = floorf(z);
        float fx = x - x0f, fy = y - y0f, fz = z - z0f;
        int ix0 = (int)x0f, iy0 = (int)y0f, iz0 = (int)z0f;
        float ap = wt[p] * invs;
#pragma unroll
        for (int dz = 0; dz < 2; dz++) {
            int zi = iz0 + dz;
            if ((unsigned)zi >= DDEP) continue;
            float wz = dz ? fz : (1.f - fz);
#pragma unroll
            for (int dy = 0; dy < 2; dy++) {
                int yi = iy0 + dy;
                if ((unsigned)yi >= HH) continue;
                float wzy = wz * (dy ? fy : (1.f - fy));
#pragma unroll
                for (int dx = 0; dx < 2; dx++) {
                    int xi = ix0 + dx;
                    if ((unsigned)xi >= WW) continue;
                    float wgt = wzy * (dx ? fx : (1.f - fx));
                    int idx = (zi * HH + yi) * WW + xi;
                    acc += ap * wgt * __half2float(__ldg(&vbh[(size_t)idx * EE]));
                }
            }
        }
    }
    unsigned short h, l;
    splith(acc, h, l);
    size_t oidx = row * EE + head * HD + lane;
    oh[oidx] = reinterpret_cast<__half&>(h);
    ol[oidx] = reinterpret_cast<__half&>(l);
}

// ================= launch ==================================================
extern "C" void kernel_launch(void* const* d_in, const int* in_sizes, int n_in,
                              void* d_out, int out_size) {
    const float* query  = (const float*)d_in[0];
    const float* value  = (const float*)d_in[1];
    const float* qpos   = (const float*)d_in[2];
    const float* W_off  = (const float*)d_in[3];
    const float* b_off  = (const float*)d_in[4];
    const float* W_attn = (const float*)d_in[5];
    const float* b_attn = (const float*)d_in[6];
    const float* W_v    = (const float*)d_in[7];
    const float* b_v    = (const float*)d_in[8];
    const float* W_out  = (const float*)d_in[9];
    const float* b_out  = (const float*)d_in[10];
    float* out = (float*)d_out;

    float *oa_s, *boa_s;
    __half *vf, *vh, *qh, *sph, *spl, *wvh, *woa, *wuh;
    cudaGetSymbolAddress((void**)&oa_s,  g_oa);
    cudaGetSymbolAddress((void**)&boa_s, g_boa);
    cudaGetSymbolAddress((void**)&vf,  g_vf);
    cudaGetSymbolAddress((void**)&vh,  g_vh);
    cudaGetSymbolAddress((void**)&qh,  g_qh);
    cudaGetSymbolAddress((void**)&sph, g_sph); cudaGetSymbolAddress((void**)&spl, g_spl);
    cudaGetSymbolAddress((void**)&wvh, g_wvh);
    cudaGetSymbolAddress((void**)&woa, g_woa);
    cudaGetSymbolAddress((void**)&wuh, g_wuh);

    static int smem_set = 0;
    if (!smem_set) {
        cudaFuncSetAttribute(gemm_f16<1,0>, cudaFuncAttributeMaxDynamicSharedMemorySize, SMEM_TOT);
        cudaFuncSetAttribute(gemm_f16<1,1>, cudaFuncAttributeMaxDynamicSharedMemorySize, SMEM_TOT);
        cudaFuncSetAttribute(gemm_f16<2,0>, cudaFuncAttributeMaxDynamicSharedMemorySize, SMEM_TOT);
        smem_set = 1;
    }

    // 1) weight conversions (hi only everywhere)
    {
        int n4 = (EE * EE) / 4;
        split1_kernel<<<(n4 + 255) / 256, 256>>>((const float4*)W_v, (uint2*)wvh, n4);
        split1_kernel<<<(n4 + 255) / 256, 256>>>((const float4*)W_out, (uint2*)wuh, n4);
        int no = EE * NOFF;
        split1_strided<<<(no + 255) / 256, 256>>>(W_off, woa, EE, NOFF, 0);
        int na = EE * NATT;
        split1_strided<<<(na + 255) / 256, 256>>>(W_attn, woa, EE, NATT, NOFF);
        combine_bias<<<(NOA + 255) / 256, 256>>>(b_off, b_attn, boa_s);
    }
    // 2) value -> fp16 hi
    {
        int n4 = (BSZ * NV * EE) / 4;
        split1_kernel<<<(n4 + 255) / 256, 256>>>((const float4*)value, (uint2*)vh, n4);
    }
    // 3) v = value @ W_v + b_v  (M=51200, N=576) -> fp16, 1-product
    {
        dim3 grid(EE / BN, (BSZ * NV) / BM);
        gemm_f16<1,1><<<grid, 256, SMEM_TOT>>>(vh, nullptr, wvh, nullptr, b_v, vf, BSZ * NV, EE, EE);
    }
    // 4) q = query + query_pos (hi only)
    {
        int n4 = (BSZ * NQ * EE) / 4;
        split_add1_kernel<<<(n4 + 255) / 256, 256>>>(
            (const float4*)query, (const float4*)qpos, (uint2*)qh, n4);
    }
    // 5) combined offs|attn = q @ [W_off|W_attn] + [b_off|b_attn]  (N=864)
    {
        dim3 grid(NOA / BN, (BSZ * NQ) / BM);
        gemm_f16<1,0><<<grid, 256, SMEM_TOT>>>(qh, nullptr, woa, nullptr, boa_s, oa_s, BSZ * NQ, NOA, EE);
    }
    // 6) trilinear sampling + softmax weighting -> fp16 hi/lo
    {
        int warps = BSZ * HEADS * NQ;
        int blocks = (warps + 7) / 8;
        deform_sample<<<blocks, 256>>>(vf, oa_s, sph, spl);
    }
    // 7) out = samp @ W_out + b_out  (N=576), 2-product
    {
        dim3 grid(EE / BN, (BSZ * NQ) / BM);
        gemm_f16<2,0><<<grid, 256, SMEM_TOT>>>(sph, spl, wuh, nullptr, b_out, out, BSZ * NQ, EE, EE);
    }
}

// round 11
// speedup vs baseline: 1.4195x; 1.0495x over previous
#include <cuda_runtime.h>
#include <cuda_fp16.h>
#include <cstdint>
#include <math.h>

#define BSZ 2
#define HH 64
#define WW 80
#define NQ (HH*WW)          // 5120
#define EE 576
#define HEADS 18
#define HD 32
#define NPTS 12
#define NFR 3
#define DDEP 5
#define NV (NQ*DDEP)        // 25600
#define NOFF (HEADS*NPTS*3) // 648
#define NATT (HEADS*NPTS)   // 216
#define NOA  (NOFF+NATT)    // 864

// ---------------- scratch (device globals; no allocation allowed) ----------
__device__ float g_oa  [(size_t)BSZ*NQ*NOA];
__device__ float g_boa [NOA];

__device__ __align__(128) __half g_vf  [(size_t)BSZ*NV*EE];   // projected v, fp16
__device__ __align__(128) __half g_vh  [(size_t)BSZ*NV*EE];   // value hi
__device__ __align__(128) __half g_qh  [(size_t)BSZ*NQ*EE];   // q hi
__device__ __align__(128) __half g_sph [(size_t)BSZ*NQ*EE];   // samp (fp16)
__device__ __align__(128) __half g_wvh [(size_t)EE*EE];       // W_v hi
__device__ __align__(128) __half g_woa [(size_t)EE*NOA];      // [W_off|W_attn] hi
__device__ __align__(128) __half g_wuh [(size_t)EE*EE];       // W_out hi

// ================= helpers =================================================
__device__ __forceinline__ uint32_t smem_u32(const void* p) {
    uint32_t a;
    asm("{ .reg .u64 t; cvta.to.shared.u64 t, %1; cvt.u32.u64 %0, t; }" : "=r"(a) : "l"(p));
    return a;
}
__device__ __forceinline__ void ldsm_x4(uint32_t* r, uint32_t addr) {
    asm volatile("ldmatrix.sync.aligned.m8n8.x4.shared.b16 {%0,%1,%2,%3}, [%4];"
                 : "=r"(r[0]), "=r"(r[1]), "=r"(r[2]), "=r"(r[3]) : "r"(addr));
}
__device__ __forceinline__ void ldsm_x4_t(uint32_t* r, uint32_t addr) {
    asm volatile("ldmatrix.sync.aligned.m8n8.x4.trans.shared.b16 {%0,%1,%2,%3}, [%4];"
                 : "=r"(r[0]), "=r"(r[1]), "=r"(r[2]), "=r"(r[3]) : "r"(addr));
}
__device__ __forceinline__ void mma_f16(float* c, const uint32_t* a, const uint32_t* b) {
    asm volatile(
        "mma.sync.aligned.m16n8k16.row.col.f32.f16.f16.f32 "
        "{%0,%1,%2,%3}, {%4,%5,%6,%7}, {%8,%9}, {%0,%1,%2,%3};"
        : "+f"(c[0]), "+f"(c[1]), "+f"(c[2]), "+f"(c[3])
        : "r"(a[0]), "r"(a[1]), "r"(a[2]), "r"(a[3]), "r"(b[0]), "r"(b[1]));
}
__device__ __forceinline__ void cp16(uint32_t dst, const void* src) {
    asm volatile("cp.async.ca.shared.global [%0], [%1], 16;" :: "r"(dst), "l"(src));
}
__device__ __forceinline__ void cp16p(uint32_t dst, const void* src, int srcsize) {
    asm volatile("cp.async.ca.shared.global [%0], [%1], 16, %2;" :: "r"(dst), "l"(src), "r"(srcsize));
}
#define CP_COMMIT() asm volatile("cp.async.commit_group;" ::: "memory")
#define CP_WAIT1()  asm volatile("cp.async.wait_group 1;" ::: "memory")

__device__ __forceinline__ void splith(float f, unsigned short& h, unsigned short& l) {
    __half hh = __float2half_rn(f);
    float r = f - __half2float(hh);
    __half hl = __float2half_rn(r);
    h = reinterpret_cast<unsigned short&>(hh);
    l = reinterpret_cast<unsigned short&>(hl);
}
__device__ __forceinline__ uint2 hi4(float4 v) {
    __half2 a = __floats2half2_rn(v.x, v.y);
    __half2 b = __floats2half2_rn(v.z, v.w);
    uint2 r;
    r.x = reinterpret_cast<uint32_t&>(a);
    r.y = reinterpret_cast<uint32_t&>(b);
    return r;
}

// ================= fused weight conversion =================================
// Converts W_v, W_out (contiguous), W_off, W_attn (strided into combined) and
// the combined bias, in ONE kernel via block-range dispatch.
#define NB_WV   324                      // (EE*EE/4)/256
#define NB_WU   324
#define NB_WO   1458                     // (EE*NOFF)/256
#define NB_WA   486                      // (EE*NATT)/256
#define NB_BIAS 4
__global__ void convert_weights(const float4* __restrict__ W_v, const float4* __restrict__ W_out,
                                const float* __restrict__ W_off, const float* __restrict__ W_attn,
                                const float* __restrict__ b_off, const float* __restrict__ b_attn,
                                uint2* __restrict__ wvh, uint2* __restrict__ wuh,
                                __half* __restrict__ woa, float* __restrict__ boa) {
    int blk = blockIdx.x;
    if (blk < NB_WV) {
        int i = blk * 256 + threadIdx.x;
        if (i < (EE * EE) / 4) wvh[i] = hi4(W_v[i]);
    } else if (blk < NB_WV + NB_WU) {
        int i = (blk - NB_WV) * 256 + threadIdx.x;
        if (i < (EE * EE) / 4) wuh[i] = hi4(W_out[i]);
    } else if (blk < NB_WV + NB_WU + NB_WO) {
        int i = (blk - NB_WV - NB_WU) * 256 + threadIdx.x;
        if (i < EE * NOFF) {
            int k = i / NOFF, n = i % NOFF;
            woa[(size_t)k * NOA + n] = __float2half_rn(W_off[i]);
        }
    } else if (blk < NB_WV + NB_WU + NB_WO + NB_WA) {
        int i = (blk - NB_WV - NB_WU - NB_WO) * 256 + threadIdx.x;
        if (i < EE * NATT) {
            int k = i / NATT, n = i % NATT;
            woa[(size_t)k * NOA + NOFF + n] = __float2half_rn(W_attn[i]);
        }
    } else {
        int i = (blk - NB_WV - NB_WU - NB_WO - NB_WA) * 256 + threadIdx.x;
        if (i < NOA) boa[i] = (i < NOFF) ? b_off[i] : b_attn[i - NOFF];
    }
}

// hi-only split
__global__ void split1_kernel(const float4* __restrict__ in, uint2* __restrict__ hi, int n4) {
    int i = blockIdx.x * blockDim.x + threadIdx.x;
    if (i < n4) hi[i] = hi4(in[i]);
}
// q = a + b, hi only
__global__ void split_add1_kernel(const float4* __restrict__ a, const float4* __restrict__ b,
                                  uint2* __restrict__ hi, int n4) {
    int i = blockIdx.x * blockDim.x + threadIdx.x;
    if (i < n4) {
        float4 x = a[i], y = b[i];
        hi[i] = hi4(make_float4(x.x + y.x, x.y + y.y, x.z + y.z, x.w + y.w));
    }
}

// ================= fp16 HMMA GEMM with cp.async pipeline ===================
// NPROD=1: AhBh ; NPROD=2: AhBh+AlBh
// OUTF16: 0 = fp32 output, 1 = fp16 output.
#define BM 128
#define BN 96
#define BK 32
#define STAGES 3
#define SA 80
#define SB 208
#define A_BYTES (128*SA)
#define B_BYTES (32*SB)
#define OFF_AH 0
#define OFF_AL A_BYTES
#define OFF_BH (2*A_BYTES)
#define STAGE_SZ (2*A_BYTES + 2*B_BYTES)   // 33792
#define SMEM_TOT (STAGES*STAGE_SZ)         // 101376

template<int NPROD, int OUTF16>
__global__ __launch_bounds__(256, 2)
void gemm_f16(const __half* __restrict__ Ah, const __half* __restrict__ Al,
              const __half* __restrict__ Bh,
              const float* __restrict__ bias, void* __restrict__ Cv,
              int M, int N, int K) {
    extern __shared__ char smem[];
    uint32_t sbase = smem_u32(smem);
    const int tid = threadIdx.x;
    const int lane = tid & 31, wid = tid >> 5;
    const int warp_m = wid & 3, warp_n = wid >> 2;
    const int bm = blockIdx.y * BM;
    const int bn = blockIdx.x * BN;
    const int nchunk = K / BK;

    auto load_chunk = [&](int c, int s) {
        const int k0 = c * BK;
        char* sb = smem + s * STAGE_SZ;
#pragma unroll
        for (int t = 0; t < 2; t++) {
            int idx = tid + t * 256, r = idx >> 2, c4 = idx & 3;
            uint32_t dst = smem_u32(sb + OFF_AH + r * SA + c4 * 16);
            cp16(dst, &Ah[(size_t)(bm + r) * K + k0 + c4 * 8]);
            if (NPROD >= 2)
                cp16(dst + A_BYTES, &Al[(size_t)(bm + r) * K + k0 + c4 * 8]);
        }
#pragma unroll
        for (int t = 0; t < 2; t++) {
            int idx = tid + t * 256;
            if (idx < 384) {
                int r = idx / 12, g = idx % 12;
                int col = bn + g * 8;
                int sz = (col < N) ? 16 : 0;
                uint32_t dst = smem_u32(sb + OFF_BH + r * SB + g * 16);
                cp16p(dst, &Bh[(size_t)(k0 + r) * N + col], sz);
            }
        }
    };

    float acc[2][6][4];
#pragma unroll
    for (int mi = 0; mi < 2; mi++)
#pragma unroll
        for (int ni = 0; ni < 6; ni++)
#pragma unroll
            for (int j = 0; j < 4; j++) acc[mi][ni][j] = 0.f;

    load_chunk(0, 0); CP_COMMIT();
    load_chunk(1, 1); CP_COMMIT();

    for (int c = 0; c < nchunk; c++) {
        CP_WAIT1();
        // single barrier per chunk: all warps have finished computing the
        // stage about to be overwritten (c-1 mod 3) before loads are issued.
        __syncthreads();
        if (c + 2 < nchunk) load_chunk(c + 2, (c + 2) % STAGES);
        CP_COMMIT();

        uint32_t sbuf = sbase + (c % STAGES) * STAGE_SZ;
#pragma unroll
        for (int ks = 0; ks < 2; ks++) {
            uint32_t a_hi[2][4], a_lo[2][4], b_hi[6][2];
#pragma unroll
            for (int mi = 0; mi < 2; mi++) {
                uint32_t ad = sbuf + OFF_AH
                    + (warp_m * 32 + mi * 16 + (lane & 15)) * SA
                    + ks * 32 + (lane >> 4) * 16;
                ldsm_x4(a_hi[mi], ad);
                if (NPROD >= 2) ldsm_x4(a_lo[mi], ad + A_BYTES);
            }
#pragma unroll
            for (int nt = 0; nt < 3; nt++) {
                uint32_t bd = sbuf + OFF_BH
                    + (ks * 16 + (lane & 15)) * SB
                    + (warp_n * 48 + nt * 16) * 2 + (lane >> 4) * 16;
                uint32_t r[4];
                ldsm_x4_t(r, bd);
                b_hi[nt * 2][0] = r[0]; b_hi[nt * 2][1] = r[1];
                b_hi[nt * 2 + 1][0] = r[2]; b_hi[nt * 2 + 1][1] = r[3];
            }
#pragma unroll
            for (int mi = 0; mi < 2; mi++)
#pragma unroll
                for (int ni = 0; ni < 6; ni++) {
                    mma_f16(acc[mi][ni], a_hi[mi], b_hi[ni]);
                    if (NPROD >= 2) mma_f16(acc[mi][ni], a_lo[mi], b_hi[ni]);
                }
        }
    }

    __syncthreads();  // protect smem until all compute done (last stages)

    // ---- epilogue ----
    const int row_base = bm + warp_m * 32 + (lane >> 2);
    const int col_base = bn + warp_n * 48 + (lane & 3) * 2;
#pragma unroll
    for (int mi = 0; mi < 2; mi++)
#pragma unroll
        for (int r2 = 0; r2 < 2; r2++) {
            int row = row_base + mi * 16 + r2 * 8;
#pragma unroll
            for (int ni = 0; ni < 6; ni++) {
                int col = col_base + ni * 8;
                if (col < N) {
                    float ox = acc[mi][ni][r2 * 2 + 0] + bias[col];
                    float oy = acc[mi][ni][r2 * 2 + 1] + bias[col + 1];
                    if (OUTF16) {
                        __half2 pk = __floats2half2_rn(ox, oy);
                        *reinterpret_cast<__half2*>(
                            &((__half*)Cv)[(size_t)row * N + col]) = pk;
                    } else {
                        float2 o; o.x = ox; o.y = oy;
                        *reinterpret_cast<float2*>(&((float*)Cv)[(size_t)row * N + col]) = o;
                    }
                }
            }
        }
}

// ================= deformable 3D trilinear sampling (fp16 v) ===============
__global__ __launch_bounds__(256)
void deform_sample(const __half* __restrict__ v, const float* __restrict__ oa,
                   __half* __restrict__ oh) {
    int wg = (blockIdx.x * blockDim.x + threadIdx.x) >> 5;
    int lane = threadIdx.x & 31;
    const int total = BSZ * HEADS * NQ;
    if (wg >= total) return;

    int q    = wg % NQ;
    int head = (wg / NQ) % HEADS;
    int b    = wg / (NQ * HEADS);
    size_t row = (size_t)b * NQ + q;

    int qx = q % WW;
    int qy = q / WW;
    float refx = ((float)qx + 0.5f) / (float)WW;
    float refy = ((float)qy + 0.5f) / (float)HH;

    const float* lgp = oa + row * NOA + NOFF + head * NPTS;
    float wt[NPTS];
    float mx = -1e30f;
#pragma unroll
    for (int p = 0; p < NPTS; p++) mx = fmaxf(mx, lgp[p]);
    float s = 0.f;
#pragma unroll
    for (int p = 0; p < NPTS; p++) { wt[p] = expf(lgp[p] - mx); s += wt[p]; }
    float invs = 1.f / s;

    const float* offp = oa + row * NOA + head * NPTS * 3;
    const __half* vbh = v + (size_t)b * NV * EE + head * HD + lane;

    float acc = 0.f;
#pragma unroll
    for (int p = 0; p < NPTS; p++) {
        float ox = offp[p * 3 + 0];
        float oy = offp[p * 3 + 1];
        float oz = offp[p * 3 + 2];
        float x = (refx + ox / (float)WW) * (float)WW - 0.5f;
        float y = (refy + oy / (float)HH) * (float)HH - 0.5f;
        float z = (oz / (float)NFR) * (float)DDEP - 0.5f;
        float x0f = floorf(x), y0f = floorf(y), z0f = floorf(z);
        float fx = x - x0f, fy = y - y0f, fz = z - z0f;
        int ix0 = (int)x0f, iy0 = (int)y0f, iz0 = (int)z0f;
        float ap = wt[p] * invs;
#pragma unroll
        for (int dz = 0; dz < 2; dz++) {
            int zi = iz0 + dz;
            if ((unsigned)zi >= DDEP) continue;
            float wz = dz ? fz : (1.f - fz);
#pragma unroll
            for (int dy = 0; dy < 2; dy++) {
                int yi = iy0 + dy;
                if ((unsigned)yi >= HH) continue;
                float wzy = wz * (dy ? fy : (1.f - fy));
#pragma unroll
                for (int dx = 0; dx < 2; dx++) {
                    int xi = ix0 + dx;
                    if ((unsigned)xi >= WW) continue;
                    float wgt = wzy * (dx ? fx : (1.f - fx));
                    int idx = (zi * HH + yi) * WW + xi;
                    acc += ap * wgt * __half2float(__ldg(&vbh[(size_t)idx * EE]));
                }
            }
        }
    }
    oh[row * EE + head * HD + lane] = __float2half_rn(acc);
}

// ================= launch ==================================================
extern "C" void kernel_launch(void* const* d_in, const int* in_sizes, int n_in,
                              void* d_out, int out_size) {
    const float* query  = (const float*)d_in[0];
    const float* value  = (const float*)d_in[1];
    const float* qpos   = (const float*)d_in[2];
    const float* W_off  = (const float*)d_in[3];
    const float* b_off  = (const float*)d_in[4];
    const float* W_attn = (const float*)d_in[5];
    const float* b_attn = (const float*)d_in[6];
    const float* W_v    = (const float*)d_in[7];
    const float* b_v    = (const float*)d_in[8];
    const float* W_out  = (const float*)d_in[9];
    const float* b_out  = (const float*)d_in[10];
    float* out = (float*)d_out;

    float *oa_s, *boa_s;
    __half *vf, *vh, *qh, *sph, *wvh, *woa, *wuh;
    cudaGetSymbolAddress((void**)&oa_s,  g_oa);
    cudaGetSymbolAddress((void**)&boa_s, g_boa);
    cudaGetSymbolAddress((void**)&vf,  g_vf);
    cudaGetSymbolAddress((void**)&vh,  g_vh);
    cudaGetSymbolAddress((void**)&qh,  g_qh);
    cudaGetSymbolAddress((void**)&sph, g_sph);
    cudaGetSymbolAddress((void**)&wvh, g_wvh);
    cudaGetSymbolAddress((void**)&woa, g_woa);
    cudaGetSymbolAddress((void**)&wuh, g_wuh);

    static int smem_set = 0;
    if (!smem_set) {
        cudaFuncSetAttribute(gemm_f16<1,0>, cudaFuncAttributeMaxDynamicSharedMemorySize, SMEM_TOT);
        cudaFuncSetAttribute(gemm_f16<1,1>, cudaFuncAttributeMaxDynamicSharedMemorySize, SMEM_TOT);
        smem_set = 1;
    }

    // 1) fused weight conversion (one launch)
    {
        int nb = NB_WV + NB_WU + NB_WO + NB_WA + NB_BIAS;
        convert_weights<<<nb, 256>>>((const float4*)W_v, (const float4*)W_out,
                                     W_off, W_attn, b_off, b_attn,
                                     (uint2*)wvh, (uint2*)wuh, woa, boa_s);
    }
    // 2) value -> fp16 hi
    {
        int n4 = (BSZ * NV * EE) / 4;
        split1_kernel<<<(n4 + 255) / 256, 256>>>((const float4*)value, (uint2*)vh, n4);
    }
    // 3) q = query + query_pos (hi only)
    {
        int n4 = (BSZ * NQ * EE) / 4;
        split_add1_kernel<<<(n4 + 255) / 256, 256>>>(
            (const float4*)query, (const float4*)qpos, (uint2*)qh, n4);
    }
    // 4) v = value @ W_v + b_v  (M=51200, N=576) -> fp16, 1-product
    {
        dim3 grid(EE / BN, (BSZ * NV) / BM);
        gemm_f16<1,1><<<grid, 256, SMEM_TOT>>>(vh, nullptr, wvh, b_v, vf, BSZ * NV, EE, EE);
    }
    // 5) combined offs|attn = q @ [W_off|W_attn] + bias  (N=864)
    {
        dim3 grid(NOA / BN, (BSZ * NQ) / BM);
        gemm_f16<1,0><<<grid, 256, SMEM_TOT>>>(qh, nullptr, woa, boa_s, oa_s, BSZ * NQ, NOA, EE);
    }
    // 6) trilinear sampling + softmax weighting -> fp16
    {
        int warps = BSZ * HEADS * NQ;
        int blocks = (warps + 7) / 8;
        deform_sample<<<blocks, 256>>>(vf, oa_s, sph);
    }
    // 7) out = samp @ W_out + b_out  (N=576), 1-product
    {
        dim3 grid(EE / BN, (BSZ * NQ) / BM);
        gemm_f16<1,0><<<grid, 256, SMEM_TOT>>>(sph, nullptr, wuh, b_out, out, BSZ * NQ, EE, EE);
    }
}